// round 1
// baseline (speedup 1.0000x reference)
#include <cuda_runtime.h>
#include <math.h>

#define NNODES 100000
#define NEDGES 1600000
#define NB_SCAN 98   /* ceil(NNODES/1024) */

// ------------------------- device scratch (no allocs allowed) ---------------
__device__ int   g_cnt[NNODES];
__device__ int   g_rowptr[NNODES + 1];
__device__ int   g_cursor[NNODES];
__device__ int   g_col[NEDGES];
__device__ float g_dinv[NNODES];
__device__ int   g_bsums[NB_SCAN];
__device__ float g_bufA[(size_t)NNODES * 64];
__device__ float g_bufB[(size_t)NNODES * 64];
__device__ float g_buf128[(size_t)NNODES * 128];

// ------------------------------- CSR build ----------------------------------
__global__ void k_zero() {
    int i = blockIdx.x * blockDim.x + threadIdx.x;
    if (i < NNODES) { g_cnt[i] = 0; g_cursor[i] = 0; }
}

__global__ void k_count(const int* __restrict__ dst) {
    int e = blockIdx.x * blockDim.x + threadIdx.x;
    if (e < NEDGES) atomicAdd(&g_cnt[dst[e]], 1);
}

__global__ void k_bsum() {
    __shared__ int s[256];
    int t = threadIdx.x;
    int base = blockIdx.x * 1024 + t * 4;
    int sum = 0;
#pragma unroll
    for (int i = 0; i < 4; i++) { int idx = base + i; if (idx < NNODES) sum += g_cnt[idx]; }
    s[t] = sum; __syncthreads();
    for (int off = 128; off > 0; off >>= 1) {
        if (t < off) s[t] += s[t + off];
        __syncthreads();
    }
    if (t == 0) g_bsums[blockIdx.x] = s[0];
}

__global__ void k_scanbs() {
    __shared__ int s[NB_SCAN];
    int t = threadIdx.x;
    if (t < NB_SCAN) s[t] = g_bsums[t];
    __syncthreads();
    if (t == 0) {
        int run = 0;
        for (int i = 0; i < NB_SCAN; i++) { int v = s[i]; s[i] = run; run += v; }
    }
    __syncthreads();
    if (t < NB_SCAN) g_bsums[t] = s[t];
}

__global__ void k_writeptr() {
    __shared__ int s[256];
    int t = threadIdx.x;
    int base = blockIdx.x * 1024 + t * 4;
    int c[4]; int sum = 0;
#pragma unroll
    for (int i = 0; i < 4; i++) {
        int idx = base + i;
        c[i] = (idx < NNODES) ? g_cnt[idx] : 0;
        sum += c[i];
    }
    s[t] = sum; __syncthreads();
    // inclusive Hillis-Steele scan over thread sums
    for (int off = 1; off < 256; off <<= 1) {
        int v = (t >= off) ? s[t - off] : 0;
        __syncthreads();
        s[t] += v;
        __syncthreads();
    }
    int excl = s[t] - sum + g_bsums[blockIdx.x];
#pragma unroll
    for (int i = 0; i < 4; i++) {
        int idx = base + i;
        if (idx < NNODES) {
            g_rowptr[idx] = excl;
            g_dinv[idx] = rsqrtf((float)c[i] + 1.0f);
            excl += c[i];
        }
    }
    if (blockIdx.x == 0 && t == 0) g_rowptr[NNODES] = NEDGES;
}

__global__ void k_fill(const int* __restrict__ src, const int* __restrict__ dst) {
    int e = blockIdx.x * blockDim.x + threadIdx.x;
    if (e >= NEDGES) return;
    int d = dst[e];
    int pos = atomicAdd(&g_cursor[d], 1);
    g_col[g_rowptr[d] + pos] = src[e];
}

// --------------------------------- GEMM -------------------------------------
// C[N x OUTtot] = A[N x IN] @ W[IN x OUTtot], 64x64 tile per block, 256 thr,
// 4x4 register micro-tile. Epilogue: optional bias, relu, row-scale by dinv.
template <int IN, bool SCALE, bool BIAS, bool RELU>
__global__ __launch_bounds__(256) void k_gemm(
    const float* __restrict__ A, const float* __restrict__ W,
    const float* __restrict__ bias, float* __restrict__ C, int OUTtot)
{
    __shared__ float As[16][64];
    __shared__ float Ws[16][64];
    int t  = threadIdx.x;
    int tx = t & 15, ty = t >> 4;
    int row0 = blockIdx.x * 64;
    int bn0  = blockIdx.y * 64;

    float acc[4][4] = {};

    int lr = t >> 2;            // A-load: row within tile (0..63)
    int lk = (t & 3) * 4;       // A-load: k quad
    int wk = t >> 4;            // W-load: k (0..15)
    int wn = (t & 15) * 4;      // W-load: col quad

    for (int kk = 0; kk < IN; kk += 16) {
        float4 av = make_float4(0.f, 0.f, 0.f, 0.f);
        int gr = row0 + lr;
        if (gr < NNODES)
            av = *(const float4*)&A[(size_t)gr * IN + kk + lk];
        As[lk + 0][lr] = av.x; As[lk + 1][lr] = av.y;
        As[lk + 2][lr] = av.z; As[lk + 3][lr] = av.w;

        *(float4*)&Ws[wk][wn] =
            *(const float4*)&W[(size_t)(kk + wk) * OUTtot + bn0 + wn];
        __syncthreads();

#pragma unroll
        for (int k = 0; k < 16; k++) {
            float4 a = *(const float4*)&As[k][ty * 4];
            float4 b = *(const float4*)&Ws[k][tx * 4];
            acc[0][0] += a.x * b.x; acc[0][1] += a.x * b.y;
            acc[0][2] += a.x * b.z; acc[0][3] += a.x * b.w;
            acc[1][0] += a.y * b.x; acc[1][1] += a.y * b.y;
            acc[1][2] += a.y * b.z; acc[1][3] += a.y * b.w;
            acc[2][0] += a.z * b.x; acc[2][1] += a.z * b.y;
            acc[2][2] += a.z * b.z; acc[2][3] += a.z * b.w;
            acc[3][0] += a.w * b.x; acc[3][1] += a.w * b.y;
            acc[3][2] += a.w * b.z; acc[3][3] += a.w * b.w;
        }
        __syncthreads();
    }

    float4 bj = make_float4(0.f, 0.f, 0.f, 0.f);
    if (BIAS) bj = *(const float4*)&bias[bn0 + tx * 4];
#pragma unroll
    for (int i = 0; i < 4; i++) {
        int r = row0 + ty * 4 + i;
        if (r >= NNODES) continue;
        float4 v = make_float4(acc[i][0] + bj.x, acc[i][1] + bj.y,
                               acc[i][2] + bj.z, acc[i][3] + bj.w);
        if (RELU) {
            v.x = fmaxf(v.x, 0.f); v.y = fmaxf(v.y, 0.f);
            v.z = fmaxf(v.z, 0.f); v.w = fmaxf(v.w, 0.f);
        }
        if (SCALE) {
            float di = g_dinv[r];
            v.x *= di; v.y *= di; v.z *= di; v.w *= di;
        }
        *(float4*)&C[(size_t)r * OUTtot + bn0 + tx * 4] = v;
    }
}

// ----------------------------- Aggregation -----------------------------------
// One warp per destination node, 64-dim features (2 floats / lane).
// In: U = dinv-prescaled features. Out = dinv[d]*(U[d] + sum_{s->d} U[s]),
// then optional +bias, relu, and *dinv[d] again (prescale for next agg).
template <bool BIAS, bool RELU, bool POSTSCALE>
__global__ __launch_bounds__(256) void k_agg64(
    const float* __restrict__ U, const float* __restrict__ bias,
    float* __restrict__ Out)
{
    int warp = (blockIdx.x * blockDim.x + threadIdx.x) >> 5;
    int lane = threadIdx.x & 31;
    if (warp >= NNODES) return;
    int d = warp;

    float2 acc  = *(const float2*)&U[(size_t)d * 64 + 2 * lane];   // self loop
    float2 acc2 = make_float2(0.f, 0.f);

    int b = g_rowptr[d], e = g_rowptr[d + 1];
    int j = b;
    for (; j + 1 < e; j += 2) {
        int s0 = __ldg(&g_col[j]);
        int s1 = __ldg(&g_col[j + 1]);
        float2 v0 = *(const float2*)&U[(size_t)s0 * 64 + 2 * lane];
        float2 v1 = *(const float2*)&U[(size_t)s1 * 64 + 2 * lane];
        acc.x  += v0.x; acc.y  += v0.y;
        acc2.x += v1.x; acc2.y += v1.y;
    }
    if (j < e) {
        int s0 = __ldg(&g_col[j]);
        float2 v0 = *(const float2*)&U[(size_t)s0 * 64 + 2 * lane];
        acc.x += v0.x; acc.y += v0.y;
    }
    acc.x += acc2.x; acc.y += acc2.y;

    float di = g_dinv[d];
    float ox = acc.x * di, oy = acc.y * di;
    if (BIAS) { ox += bias[2 * lane]; oy += bias[2 * lane + 1]; }
    if (RELU) { ox = fmaxf(ox, 0.f); oy = fmaxf(oy, 0.f); }
    if (POSTSCALE) { ox *= di; oy *= di; }
    *(float2*)&Out[(size_t)d * 64 + 2 * lane] = make_float2(ox, oy);
}

// ------------------------------- launch --------------------------------------
extern "C" void kernel_launch(void* const* d_in, const int* in_sizes, int n_in,
                              void* d_out, int out_size)
{
    const float* x  = (const float*)d_in[0];
    const int*   ei = (const int*)d_in[1];
    const float* W1 = (const float*)d_in[2];
    const float* b1 = (const float*)d_in[3];
    const float* W2 = (const float*)d_in[4];
    const float* b2 = (const float*)d_in[5];
    const float* W3 = (const float*)d_in[6];
    const float* b3 = (const float*)d_in[7];
    float* out = (float*)d_out;

    const int* src = ei;
    const int* dst = ei + NEDGES;

    float *bufA, *bufB, *buf128;
    cudaGetSymbolAddress((void**)&bufA,   g_bufA);
    cudaGetSymbolAddress((void**)&bufB,   g_bufB);
    cudaGetSymbolAddress((void**)&buf128, g_buf128);

    const int EB = (NEDGES + 255) / 256;          // 6250
    const int GB = (NNODES + 63) / 64;            // 1563 gemm row-tiles
    const int AB = (NNODES * 32 + 255) / 256;     // 12500 agg blocks (8 warps)

    // --- CSR build (shared by all 3 layers) ---
    k_zero<<<(NNODES + 255) / 256, 256>>>();
    k_count<<<EB, 256>>>(dst);
    k_bsum<<<NB_SCAN, 256>>>();
    k_scanbs<<<1, 128>>>();
    k_writeptr<<<NB_SCAN, 256>>>();
    k_fill<<<EB, 256>>>(src, dst);

    // --- Layer 1: u1 = dinv*(x@W1); t = relu(dinv*S(u1)+b1)*dinv ---
    k_gemm<128, true, false, false><<<dim3(GB, 1), 256>>>(x, W1, nullptr, bufA, 64);
    k_agg64<true, true, true><<<AB, 256>>>(bufA, b1, bufB);

    // --- Layer 2: a2 = dinv*S(t); y2 = relu(a2@W2 + b2) ---
    k_agg64<false, false, false><<<AB, 256>>>(bufB, nullptr, bufA);
    k_gemm<64, false, true, true><<<dim3(GB, 2), 256>>>(bufA, W2, b2, buf128, 128);

    // --- Layer 3: u3 = dinv*(y2@W3); out = dinv*S(u3) + b3 ---
    k_gemm<128, true, false, false><<<dim3(GB, 1), 256>>>(buf128, W3, nullptr, bufA, 64);
    k_agg64<true, false, false><<<AB, 256>>>(bufA, b3, out);

    (void)in_sizes; (void)n_in; (void)out_size;
}